// round 2
// baseline (speedup 1.0000x reference)
#include <cuda_runtime.h>
#include <math.h>

#define NB 4
#define NPTS 4096
#define KNN 16
#define DPf 64
#define DMf 128
#define M1 (NB*NPTS)          /* 16384  */
#define M2 (M1*KNN)           /* 262144 */
#define EPSV 1e-8f

// ---------------- scratch (static device globals; no allocation) ----------------
// Big-buffer lifetime reuse:
//   g_bufA : h1  -> t  -> a
//   g_bufB : qk  -> h2
//   g_pe   : pos_enc (live until final stage)
__device__ float g_x [(size_t)M1*DMf];
__device__ float g_q [(size_t)M1*DMf];
__device__ float g_kf[(size_t)M1*DMf];
__device__ float g_vf[(size_t)M1*DMf];
__device__ int   g_idx[M1*KNN];
__device__ float g_sim[M2];
__device__ float g_bufA[(size_t)M2*DMf];
__device__ float g_bufB[(size_t)M2*DMf];
__device__ float g_pe  [(size_t)M2*DMf];

// ---------------- KNN: warp per query, stable (dist,idx) top-16 ----------------
__global__ void knn_kernel(const float* __restrict__ xyz) {
    int warp = threadIdx.x >> 5;
    int lane = threadIdx.x & 31;
    int row  = blockIdx.x * 4 + warp;            // [0, M1)
    int b = row >> 12;
    int n = row & (NPTS - 1);
    const float* xb = xyz + (size_t)b * NPTS * 3;
    float qx = xb[n*3+0], qy = xb[n*3+1], qz = xb[n*3+2];
    float sq = qx*qx + qy*qy + qz*qz;

    unsigned long long best[16];
#pragma unroll
    for (int i = 0; i < 16; i++) best[i] = ~0ULL;

    for (int t = 0; t < NPTS/32; t++) {
        int j = t*32 + lane;
        float x = xb[j*3+0], y = xb[j*3+1], z = xb[j*3+2];
        float sj = x*x + y*y + z*z;
        float d = sq + sj - 2.0f*(qx*x + qy*y + qz*z);   // exact reference formula
        unsigned u = __float_as_uint(d);
        u = (u & 0x80000000u) ? ~u : (u | 0x80000000u);  // order-preserving map
        unsigned long long key = ((unsigned long long)u << 32) | (unsigned)j;
        if (key < best[15]) {
            int p = 15;
            while (p > 0 && best[p-1] > key) { best[p] = best[p-1]; p--; }
            best[p] = key;
        }
    }

    __shared__ unsigned long long sh[4][512];
#pragma unroll
    for (int i = 0; i < 16; i++) sh[warp][lane*16 + i] = best[i];
    __syncwarp();

    int p = 0;
    for (int r = 0; r < 16; r++) {
        unsigned long long v = (p < 16) ? sh[warp][lane*16 + p] : ~0ULL;
        unsigned long long m = v;
#pragma unroll
        for (int off = 16; off; off >>= 1) {
            unsigned long long o = __shfl_xor_sync(0xffffffffu, m, off);
            m = (o < m) ? o : m;
        }
        if (v == m) { g_idx[row*KNN + r] = (int)(m & 0xffffffffu); p++; }
        __syncwarp();
    }
}

// ---------------- generic fp32 GEMM: C[M x 128] = A[M x Ka] @ W[Ka x 128] ----------------
// MODE 0: C = A@W (+bias)          MODE 1: C = A@W + bias + add + simv⊗simw0
// MODE 2: C = relu(A@W + bias)
template<int MODE>
__global__ void gemm_kernel(const float* __restrict__ A, int lda, int Ka,
                            const float* __restrict__ W,
                            const float* __restrict__ bias,
                            float* __restrict__ C,
                            const float* __restrict__ add,
                            const float* __restrict__ simv,
                            const float* __restrict__ simw0) {
    __shared__ float As[32][129];
    __shared__ float Ws[32][128];
    int bm  = blockIdx.x * 128;
    int tid = threadIdx.x;           // 256
    int tm  = tid >> 4, tn = tid & 15;

    float acc[8][8];
#pragma unroll
    for (int i = 0; i < 8; i++)
#pragma unroll
        for (int j = 0; j < 8; j++) acc[i][j] = 0.0f;

    for (int k0 = 0; k0 < Ka; k0 += 32) {
        // A tile 128x32 -> transposed to As[k][m]
#pragma unroll
        for (int pss = 0; pss < 4; pss++) {
            int idx4 = pss*256 + tid;     // 1024 float4 total
            int r  = idx4 >> 3;           // row 0..127
            int c4 = idx4 & 7;            // float4 col 0..7
            float4 v = *(const float4*)(A + (size_t)(bm + r)*lda + k0 + c4*4);
            As[c4*4+0][r] = v.x; As[c4*4+1][r] = v.y;
            As[c4*4+2][r] = v.z; As[c4*4+3][r] = v.w;
        }
        // W tile 32x128
#pragma unroll
        for (int pss = 0; pss < 4; pss++) {
            int idx4 = pss*256 + tid;
            int r  = idx4 >> 5;
            int c4 = idx4 & 31;
            *(float4*)&Ws[r][c4*4] = *(const float4*)(W + (size_t)(k0 + r)*128 + c4*4);
        }
        __syncthreads();
#pragma unroll
        for (int kk = 0; kk < 32; kk++) {
            float a[8], bb[8];
#pragma unroll
            for (int i = 0; i < 8; i++) a[i]  = As[kk][tm*8 + i];
#pragma unroll
            for (int j = 0; j < 8; j++) bb[j] = Ws[kk][tn*8 + j];
#pragma unroll
            for (int i = 0; i < 8; i++)
#pragma unroll
                for (int j = 0; j < 8; j++) acc[i][j] += a[i]*bb[j];
        }
        __syncthreads();
    }

#pragma unroll
    for (int i = 0; i < 8; i++) {
        size_t row = (size_t)bm + tm*8 + i;
#pragma unroll
        for (int j = 0; j < 8; j++) {
            int col = tn*8 + j;
            float v = acc[i][j];
            if (bias) v += bias[col];
            if (MODE == 1) v += add[row*128 + col] + simv[row]*simw0[col];
            if (MODE == 2) v = fmaxf(v, 0.0f);
            C[row*128 + col] = v;
        }
    }
}

// ---------------- block reduce (128 threads) of a float2 ----------------
__device__ __forceinline__ float2 blockReduce2(float a, float b, float* sbuf) {
    int lane = threadIdx.x & 31, w = threadIdx.x >> 5;
#pragma unroll
    for (int off = 16; off; off >>= 1) {
        a += __shfl_down_sync(0xffffffffu, a, off);
        b += __shfl_down_sync(0xffffffffu, b, off);
    }
    if (lane == 0) { sbuf[w*2] = a; sbuf[w*2+1] = b; }
    __syncthreads();
    if (threadIdx.x == 0) {
        float sa = 0, sb = 0;
        for (int i = 0; i < 4; i++) { sa += sbuf[i*2]; sb += sbuf[i*2+1]; }
        sbuf[0] = sa; sbuf[1] = sb;
    }
    __syncthreads();
    float2 r = make_float2(sbuf[0], sbuf[1]);
    __syncthreads();
    return r;
}

// ---------------- stage D: gather + sim + q-k + pos-enc hidden ----------------
// writes: g_sim, g_bufB (= q-k), g_bufA (= relu(rel_pos @ d1 + b))
__global__ void stage_d(const float* __restrict__ xyz,
                        const float* __restrict__ d1_w,
                        const float* __restrict__ d1_b) {
    int row = blockIdx.x;            // [0, M1)
    int f = threadIdx.x;             // 128
    int b = row >> 12;
    int n = row & (NPTS - 1);
    __shared__ float sbuf[8];

    float qf = g_q[(size_t)row*DMf + f];
    float2 s = blockReduce2(qf*qf, 0.0f, sbuf);
    float qn = fmaxf(sqrtf(s.x), EPSV);
    const float* xb = xyz + (size_t)b*NPTS*3;
    float qx = xb[n*3+0], qy = xb[n*3+1], qz = xb[n*3+2];
    float w0 = d1_w[f], w1 = d1_w[128+f], w2 = d1_w[256+f], bb = d1_b[f];

    for (int k = 0; k < KNN; k++) {
        int idx = g_idx[row*KNN + k];
        float kf = g_kf[((size_t)(b*NPTS + idx))*DMf + f];
        float2 dv = blockReduce2(qf*kf, kf*kf, sbuf);
        float kn = fmaxf(sqrtf(dv.y), EPSV);
        float sim = dv.x / (qn * kn);
        if (f == 0) g_sim[row*KNN + k] = sim;
        size_t orow = ((size_t)row*KNN + k)*DMf;
        g_bufB[orow + f] = qf - kf;
        float cx = qx - xb[idx*3+0];
        float cy = qy - xb[idx*3+1];
        float cz = qz - xb[idx*3+2];
        float h = cx*w0 + cy*w1 + cz*w2 + bb;
        g_bufA[orow + f] = fmaxf(h, 0.0f);
    }
}

// ---------------- stage F: softmax over K, weighted sum, fc2 + residual ----------------
// reads g_bufA (= pre-softmax attn logits), g_pe, g_vf; writes out
__global__ void stage_f(const float* __restrict__ features,
                        const float* __restrict__ fc2_w,
                        const float* __restrict__ fc2_b,
                        float* __restrict__ out) {
    int row = blockIdx.x;            // [0, M1)
    int f = threadIdx.x;             // 128
    int b = row >> 12;
    const float scale = 1.0f / sqrtf(128.0f);

    float a[KNN];
    float mx = -3.4e38f;
#pragma unroll
    for (int k = 0; k < KNN; k++) {
        a[k] = g_bufA[((size_t)row*KNN + k)*DMf + f] * scale;
        mx = fmaxf(mx, a[k]);
    }
    float sum = 0.0f;
#pragma unroll
    for (int k = 0; k < KNN; k++) { a[k] = expf(a[k] - mx); sum += a[k]; }
    float inv = 1.0f / sum;

    float* out_attn = out + (size_t)M1*DPf;
    float r = 0.0f;
#pragma unroll
    for (int k = 0; k < KNN; k++) {
        float at = a[k] * inv;
        size_t orow = ((size_t)row*KNN + k)*DMf;
        out_attn[orow + f] = at;
        int idx = g_idx[row*KNN + k];
        float v = g_vf[((size_t)(b*NPTS + idx))*DMf + f] + g_pe[orow + f];
        r += at * v;
    }
    __shared__ float rs[DMf];
    rs[f] = r;
    __syncthreads();
    if (f < DPf) {
        float o = fc2_b[f];
#pragma unroll 8
        for (int j = 0; j < DMf; j++) o += rs[j] * fc2_w[j*DPf + f];
        o += features[(size_t)row*DPf + f];
        out[(size_t)row*DPf + f] = o;
    }
}

// address-taking helpers for kernels that take scratch pointers as args
__global__ void noop_kernel() {}

// ---------------- launch ----------------
extern "C" void kernel_launch(void* const* d_in, const int* in_sizes, int n_in,
                              void* d_out, int out_size) {
    const float* xyz   = (const float*)d_in[0];
    const float* feat  = (const float*)d_in[1];
    const float* fc1_w = (const float*)d_in[2];
    const float* fc1_b = (const float*)d_in[3];
    const float* fc2_w = (const float*)d_in[4];
    const float* fc2_b = (const float*)d_in[5];
    const float* d1_w  = (const float*)d_in[6];
    const float* d1_b  = (const float*)d_in[7];
    const float* d2_w  = (const float*)d_in[8];
    const float* d2_b  = (const float*)d_in[9];
    const float* g1_w  = (const float*)d_in[10];
    const float* g1_b  = (const float*)d_in[11];
    const float* g2_w  = (const float*)d_in[12];
    const float* g2_b  = (const float*)d_in[13];
    const float* wq_w  = (const float*)d_in[14];
    const float* wk_w  = (const float*)d_in[15];
    const float* wv_w  = (const float*)d_in[16];
    const float* sim_w = (const float*)d_in[17];
    const float* sim_b = (const float*)d_in[18];
    float* out = (float*)d_out;

    // Resolve scratch addresses once per process (host statics are allowed;
    // cudaGetSymbolAddress is a non-stream, non-allocating query).
    static float *p_x = nullptr, *p_q, *p_kf, *p_vf, *p_A, *p_B, *p_pe, *p_sim;
    if (!p_x) {
        cudaGetSymbolAddress((void**)&p_x,   g_x);
        cudaGetSymbolAddress((void**)&p_q,   g_q);
        cudaGetSymbolAddress((void**)&p_kf,  g_kf);
        cudaGetSymbolAddress((void**)&p_vf,  g_vf);
        cudaGetSymbolAddress((void**)&p_sim, g_sim);
        cudaGetSymbolAddress((void**)&p_A,   g_bufA);
        cudaGetSymbolAddress((void**)&p_B,   g_bufB);
        cudaGetSymbolAddress((void**)&p_pe,  g_pe);
    }

    // 1) KNN
    knn_kernel<<<M1/4, 128>>>(xyz);

    // 2) x = features @ fc1 + b
    gemm_kernel<0><<<M1/128, 256>>>(feat, DPf, DPf, fc1_w, fc1_b, p_x, nullptr, nullptr, nullptr);

    // 3) q, k, v
    gemm_kernel<0><<<M1/128, 256>>>(p_x, DMf, DMf, wq_w, nullptr, p_q,  nullptr, nullptr, nullptr);
    gemm_kernel<0><<<M1/128, 256>>>(p_x, DMf, DMf, wk_w, nullptr, p_kf, nullptr, nullptr, nullptr);
    gemm_kernel<0><<<M1/128, 256>>>(p_x, DMf, DMf, wv_w, nullptr, p_vf, nullptr, nullptr, nullptr);

    // 4) gather + sim + (q-k)->bufB + pos-enc hidden->bufA
    stage_d<<<M1, 128>>>(xyz, d1_w, d1_b);

    // 5) pe = relu_h1(bufA) @ d2 + b
    gemm_kernel<0><<<M2/128, 256>>>(p_A, DMf, DMf, d2_w, d2_b, p_pe, nullptr, nullptr, nullptr);

    // 6) t(bufA) = qk(bufB) @ sim_w[1:] + sim*sim_w[0] + sim_b + pe
    gemm_kernel<1><<<M2/128, 256>>>(p_B, DMf, DMf, sim_w + 128, sim_b, p_A, p_pe, p_sim, sim_w);

    // 7) h2(bufB) = relu(t(bufA) @ g1 + b)
    gemm_kernel<2><<<M2/128, 256>>>(p_A, DMf, DMf, g1_w, g1_b, p_B, nullptr, nullptr, nullptr);

    // 8) a(bufA) = h2(bufB) @ g2 + b
    gemm_kernel<0><<<M2/128, 256>>>(p_B, DMf, DMf, g2_w, g2_b, p_A, nullptr, nullptr, nullptr);

    // 9) softmax + weighted sum + fc2 + residual
    stage_f<<<M1, 128>>>(feat, fc2_w, fc2_b, out);
}

// round 3
// speedup vs baseline: 1.1120x; 1.1120x over previous
#include <cuda_runtime.h>
#include <math.h>

#define NB 4
#define NPTS 4096
#define KNN 16
#define DPf 64
#define DMf 128
#define M1 (NB*NPTS)          /* 16384  */
#define M2 (M1*KNN)           /* 262144 */
#define EPSV 1e-8f

// ---------------- scratch (static device globals; no allocation) ----------------
__device__ float g_x [(size_t)M1*DMf];
__device__ float g_q [(size_t)M1*DMf];
__device__ float g_kf[(size_t)M1*DMf];
__device__ float g_vf[(size_t)M1*DMf];
__device__ int   g_idx[M1*KNN];
__device__ float g_sim[M2];
__device__ float g_bufA[(size_t)M2*DMf];
__device__ float g_bufB[(size_t)M2*DMf];
__device__ float g_pe  [(size_t)M2*DMf];

// ---------------- packed f32x2 helpers (sm_103a FFMA2 path) ----------------
__device__ __forceinline__ unsigned long long pack2(float x, float y) {
    unsigned long long r;
    asm("mov.b64 %0, {%1, %2};" : "=l"(r) : "f"(x), "f"(y));
    return r;
}
__device__ __forceinline__ float2 unpack2(unsigned long long v) {
    float2 f;
    asm("mov.b64 {%0, %1}, %2;" : "=f"(f.x), "=f"(f.y) : "l"(v));
    return f;
}
__device__ __forceinline__ void ffma2(unsigned long long& d,
                                      unsigned long long a,
                                      unsigned long long b) {
    asm("fma.rn.f32x2 %0, %1, %2, %0;" : "+l"(d) : "l"(a), "l"(b));
}

// ---------------- KNN: warp per query, stable (dist,idx) top-16 ----------------
__global__ void knn_kernel(const float* __restrict__ xyz) {
    int warp = threadIdx.x >> 5;
    int lane = threadIdx.x & 31;
    int row  = blockIdx.x * 4 + warp;            // [0, M1)
    int b = row >> 12;
    int n = row & (NPTS - 1);
    const float* xb = xyz + (size_t)b * NPTS * 3;
    float qx = xb[n*3+0], qy = xb[n*3+1], qz = xb[n*3+2];
    float sq = qx*qx + qy*qy + qz*qz;

    unsigned long long best[16];
#pragma unroll
    for (int i = 0; i < 16; i++) best[i] = ~0ULL;

    for (int t = 0; t < NPTS/32; t++) {
        int j = t*32 + lane;
        float x = xb[j*3+0], y = xb[j*3+1], z = xb[j*3+2];
        float sj = x*x + y*y + z*z;
        float d = sq + sj - 2.0f*(qx*x + qy*y + qz*z);   // exact reference formula
        unsigned u = __float_as_uint(d);
        u = (u & 0x80000000u) ? ~u : (u | 0x80000000u);  // order-preserving map
        unsigned long long key = ((unsigned long long)u << 32) | (unsigned)j;
        if (key < best[15]) {
            int p = 15;
            while (p > 0 && best[p-1] > key) { best[p] = best[p-1]; p--; }
            best[p] = key;
        }
    }

    __shared__ unsigned long long sh[4][512];
#pragma unroll
    for (int i = 0; i < 16; i++) sh[warp][lane*16 + i] = best[i];
    __syncwarp();

    int p = 0;
    for (int r = 0; r < 16; r++) {
        unsigned long long v = (p < 16) ? sh[warp][lane*16 + p] : ~0ULL;
        unsigned long long m = v;
#pragma unroll
        for (int off = 16; off; off >>= 1) {
            unsigned long long o = __shfl_xor_sync(0xffffffffu, m, off);
            m = (o < m) ? o : m;
        }
        if (v == m) { g_idx[row*KNN + r] = (int)(m & 0xffffffffu); p++; }
        __syncwarp();
    }
}

// ---------------- fp32 GEMM v2: C[M x 128] = A[M x Ka] @ W[Ka x 128] ----------------
// FFMA2 inner loop (packed f32x2), 128x128 tile, 8x8 microtile as 8x4 float2.
// MODE 0: C = A@W (+bias); gridDim.y picks among (W,C),(W2,C2),(W3,C3) for qkv batching.
// MODE 1: C = A@W + bias + add + simv*simw0
// MODE 2: C = relu(A@W + bias)
template<int MODE>
__global__ void __launch_bounds__(256, 2)
gemm_kernel(const float* __restrict__ A, int lda, int Ka,
            const float* __restrict__ W,
            const float* __restrict__ bias,
            float* __restrict__ C,
            const float* __restrict__ add,
            const float* __restrict__ simv,
            const float* __restrict__ simw0,
            const float* W2, float* C2, const float* W3, float* C3) {
    __shared__ float As[32][132];   // transposed: As[k][m], pad 132 keeps float4 align
    __shared__ float Ws[32][128];

    if (gridDim.y == 3) {
        if (blockIdx.y == 1) { W = W2; C = C2; }
        else if (blockIdx.y == 2) { W = W3; C = C3; }
    }

    int bm  = blockIdx.x * 128;
    int tid = threadIdx.x;           // 256
    int tm  = tid >> 4, tn = tid & 15;

    unsigned long long acc[8][4];
#pragma unroll
    for (int i = 0; i < 8; i++)
#pragma unroll
        for (int j = 0; j < 4; j++) acc[i][j] = 0ULL;

    for (int k0 = 0; k0 < Ka; k0 += 32) {
        // A tile 128x32 -> transposed to As[k][m]
#pragma unroll
        for (int pss = 0; pss < 4; pss++) {
            int idx4 = pss*256 + tid;     // 1024 float4 total
            int r  = idx4 >> 3;           // row 0..127
            int c4 = idx4 & 7;            // float4 col 0..7
            float4 v = *(const float4*)(A + (size_t)(bm + r)*lda + k0 + c4*4);
            As[c4*4+0][r] = v.x; As[c4*4+1][r] = v.y;
            As[c4*4+2][r] = v.z; As[c4*4+3][r] = v.w;
        }
        // W tile 32x128
#pragma unroll
        for (int pss = 0; pss < 4; pss++) {
            int idx4 = pss*256 + tid;
            int r  = idx4 >> 5;
            int c4 = idx4 & 31;
            *(float4*)&Ws[r][c4*4] = *(const float4*)(W + (size_t)(k0 + r)*128 + c4*4);
        }
        __syncthreads();
#pragma unroll
        for (int kk = 0; kk < 32; kk++) {
            float4 a0 = *(const float4*)&As[kk][tm*8];
            float4 a1 = *(const float4*)&As[kk][tm*8 + 4];
            float4 b0 = *(const float4*)&Ws[kk][tn*8];
            float4 b1 = *(const float4*)&Ws[kk][tn*8 + 4];
            unsigned long long bv[4] = { pack2(b0.x, b0.y), pack2(b0.z, b0.w),
                                         pack2(b1.x, b1.y), pack2(b1.z, b1.w) };
            unsigned long long av[8] = { pack2(a0.x, a0.x), pack2(a0.y, a0.y),
                                         pack2(a0.z, a0.z), pack2(a0.w, a0.w),
                                         pack2(a1.x, a1.x), pack2(a1.y, a1.y),
                                         pack2(a1.z, a1.z), pack2(a1.w, a1.w) };
#pragma unroll
            for (int i = 0; i < 8; i++)
#pragma unroll
                for (int j = 0; j < 4; j++) ffma2(acc[i][j], av[i], bv[j]);
        }
        __syncthreads();
    }

    // epilogue: vectorized, MODE-specific
    float bia[8];
#pragma unroll
    for (int j = 0; j < 8; j++) bia[j] = bias ? bias[tn*8 + j] : 0.0f;
    float sw0[8];
    if (MODE == 1) {
#pragma unroll
        for (int j = 0; j < 8; j++) sw0[j] = simw0[tn*8 + j];
    }

#pragma unroll
    for (int i = 0; i < 8; i++) {
        size_t row = (size_t)bm + tm*8 + i;
        float v[8];
#pragma unroll
        for (int j = 0; j < 4; j++) {
            float2 f = unpack2(acc[i][j]);
            v[2*j] = f.x + bia[2*j];
            v[2*j+1] = f.y + bia[2*j+1];
        }
        if (MODE == 1) {
            float sv = simv[row];
            const float4* ad = (const float4*)(add + row*128 + tn*8);
            float4 p0 = ad[0], p1 = ad[1];
            v[0] += p0.x + sv*sw0[0]; v[1] += p0.y + sv*sw0[1];
            v[2] += p0.z + sv*sw0[2]; v[3] += p0.w + sv*sw0[3];
            v[4] += p1.x + sv*sw0[4]; v[5] += p1.y + sv*sw0[5];
            v[6] += p1.z + sv*sw0[6]; v[7] += p1.w + sv*sw0[7];
        }
        if (MODE == 2) {
#pragma unroll
            for (int j = 0; j < 8; j++) v[j] = fmaxf(v[j], 0.0f);
        }
        float4* cp = (float4*)(C + row*128 + tn*8);
        cp[0] = make_float4(v[0], v[1], v[2], v[3]);
        cp[1] = make_float4(v[4], v[5], v[6], v[7]);
    }
}

// ---------------- block reduce (128 threads) of a float2 ----------------
__device__ __forceinline__ float2 blockReduce2(float a, float b, float* sbuf) {
    int lane = threadIdx.x & 31, w = threadIdx.x >> 5;
#pragma unroll
    for (int off = 16; off; off >>= 1) {
        a += __shfl_down_sync(0xffffffffu, a, off);
        b += __shfl_down_sync(0xffffffffu, b, off);
    }
    if (lane == 0) { sbuf[w*2] = a; sbuf[w*2+1] = b; }
    __syncthreads();
    if (threadIdx.x == 0) {
        float sa = 0, sb = 0;
        for (int i = 0; i < 4; i++) { sa += sbuf[i*2]; sb += sbuf[i*2+1]; }
        sbuf[0] = sa; sbuf[1] = sb;
    }
    __syncthreads();
    float2 r = make_float2(sbuf[0], sbuf[1]);
    __syncthreads();
    return r;
}

// ---------------- stage D: gather + sim + q-k + pos-enc hidden ----------------
__global__ void stage_d(const float* __restrict__ xyz,
                        const float* __restrict__ d1_w,
                        const float* __restrict__ d1_b) {
    int row = blockIdx.x;            // [0, M1)
    int f = threadIdx.x;             // 128
    int b = row >> 12;
    int n = row & (NPTS - 1);
    __shared__ float sbuf[8];

    float qf = g_q[(size_t)row*DMf + f];
    float2 s = blockReduce2(qf*qf, 0.0f, sbuf);
    float qn = fmaxf(sqrtf(s.x), EPSV);
    const float* xb = xyz + (size_t)b*NPTS*3;
    float qx = xb[n*3+0], qy = xb[n*3+1], qz = xb[n*3+2];
    float w0 = d1_w[f], w1 = d1_w[128+f], w2 = d1_w[256+f], bb = d1_b[f];

    for (int k = 0; k < KNN; k++) {
        int idx = g_idx[row*KNN + k];
        float kf = g_kf[((size_t)(b*NPTS + idx))*DMf + f];
        float2 dv = blockReduce2(qf*kf, kf*kf, sbuf);
        float kn = fmaxf(sqrtf(dv.y), EPSV);
        float sim = dv.x / (qn * kn);
        if (f == 0) g_sim[row*KNN + k] = sim;
        size_t orow = ((size_t)row*KNN + k)*DMf;
        g_bufB[orow + f] = qf - kf;
        float cx = qx - xb[idx*3+0];
        float cy = qy - xb[idx*3+1];
        float cz = qz - xb[idx*3+2];
        float h = cx*w0 + cy*w1 + cz*w2 + bb;
        g_bufA[orow + f] = fmaxf(h, 0.0f);
    }
}

// ---------------- stage F: softmax over K, weighted sum, fc2 + residual ----------------
__global__ void stage_f(const float* __restrict__ features,
                        const float* __restrict__ fc2_w,
                        const float* __restrict__ fc2_b,
                        float* __restrict__ out) {
    int row = blockIdx.x;            // [0, M1)
    int f = threadIdx.x;             // 128
    int b = row >> 12;
    const float scale = 1.0f / sqrtf(128.0f);

    float a[KNN];
    float mx = -3.4e38f;
#pragma unroll
    for (int k = 0; k < KNN; k++) {
        a[k] = g_bufA[((size_t)row*KNN + k)*DMf + f] * scale;
        mx = fmaxf(mx, a[k]);
    }
    float sum = 0.0f;
#pragma unroll
    for (int k = 0; k < KNN; k++) { a[k] = expf(a[k] - mx); sum += a[k]; }
    float inv = 1.0f / sum;

    float* out_attn = out + (size_t)M1*DPf;
    float r = 0.0f;
#pragma unroll
    for (int k = 0; k < KNN; k++) {
        float at = a[k] * inv;
        size_t orow = ((size_t)row*KNN + k)*DMf;
        out_attn[orow + f] = at;
        int idx = g_idx[row*KNN + k];
        float v = g_vf[((size_t)(b*NPTS + idx))*DMf + f] + g_pe[orow + f];
        r += at * v;
    }
    __shared__ float rs[DMf];
    rs[f] = r;
    __syncthreads();
    if (f < DPf) {
        float o = fc2_b[f];
#pragma unroll 8
        for (int j = 0; j < DMf; j++) o += rs[j] * fc2_w[j*DPf + f];
        o += features[(size_t)row*DPf + f];
        out[(size_t)row*DPf + f] = o;
    }
}

// ---------------- launch ----------------
extern "C" void kernel_launch(void* const* d_in, const int* in_sizes, int n_in,
                              void* d_out, int out_size) {
    const float* xyz   = (const float*)d_in[0];
    const float* feat  = (const float*)d_in[1];
    const float* fc1_w = (const float*)d_in[2];
    const float* fc1_b = (const float*)d_in[3];
    const float* fc2_w = (const float*)d_in[4];
    const float* fc2_b = (const float*)d_in[5];
    const float* d1_w  = (const float*)d_in[6];
    const float* d1_b  = (const float*)d_in[7];
    const float* d2_w  = (const float*)d_in[8];
    const float* d2_b  = (const float*)d_in[9];
    const float* g1_w  = (const float*)d_in[10];
    const float* g1_b  = (const float*)d_in[11];
    const float* g2_w  = (const float*)d_in[12];
    const float* g2_b  = (const float*)d_in[13];
    const float* wq_w  = (const float*)d_in[14];
    const float* wk_w  = (const float*)d_in[15];
    const float* wv_w  = (const float*)d_in[16];
    const float* sim_w = (const float*)d_in[17];
    const float* sim_b = (const float*)d_in[18];
    float* out = (float*)d_out;

    static float *p_x = nullptr, *p_q, *p_kf, *p_vf, *p_A, *p_B, *p_pe, *p_sim;
    if (!p_x) {
        cudaGetSymbolAddress((void**)&p_x,   g_x);
        cudaGetSymbolAddress((void**)&p_q,   g_q);
        cudaGetSymbolAddress((void**)&p_kf,  g_kf);
        cudaGetSymbolAddress((void**)&p_vf,  g_vf);
        cudaGetSymbolAddress((void**)&p_sim, g_sim);
        cudaGetSymbolAddress((void**)&p_A,   g_bufA);
        cudaGetSymbolAddress((void**)&p_B,   g_bufB);
        cudaGetSymbolAddress((void**)&p_pe,  g_pe);
    }

    // 1) KNN
    knn_kernel<<<M1/4, 128>>>(xyz);

    // 2) x = features @ fc1 + b
    gemm_kernel<0><<<M1/128, 256>>>(feat, DPf, DPf, fc1_w, fc1_b, p_x,
                                    nullptr, nullptr, nullptr,
                                    nullptr, nullptr, nullptr, nullptr);

    // 3) q, k, v batched in one launch (gridDim.y = 3)
    gemm_kernel<0><<<dim3(M1/128, 3), 256>>>(p_x, DMf, DMf, wq_w, nullptr, p_q,
                                             nullptr, nullptr, nullptr,
                                             wk_w, p_kf, wv_w, p_vf);

    // 4) gather + sim + (q-k)->bufB + pos-enc hidden->bufA
    stage_d<<<M1, 128>>>(xyz, d1_w, d1_b);

    // 5) pe = relu_h1(bufA) @ d2 + b
    gemm_kernel<0><<<M2/128, 256>>>(p_A, DMf, DMf, d2_w, d2_b, p_pe,
                                    nullptr, nullptr, nullptr,
                                    nullptr, nullptr, nullptr, nullptr);

    // 6) t(bufA) = qk(bufB) @ sim_w[1:] + sim*sim_w[0] + sim_b + pe
    gemm_kernel<1><<<M2/128, 256>>>(p_B, DMf, DMf, sim_w + 128, sim_b, p_A,
                                    p_pe, p_sim, sim_w,
                                    nullptr, nullptr, nullptr, nullptr);

    // 7) h2(bufB) = relu(t(bufA) @ g1 + b)
    gemm_kernel<2><<<M2/128, 256>>>(p_A, DMf, DMf, g1_w, g1_b, p_B,
                                    nullptr, nullptr, nullptr,
                                    nullptr, nullptr, nullptr, nullptr);

    // 8) a(bufA) = h2(bufB) @ g2 + b
    gemm_kernel<0><<<M2/128, 256>>>(p_B, DMf, DMf, g2_w, g2_b, p_A,
                                    nullptr, nullptr, nullptr,
                                    nullptr, nullptr, nullptr, nullptr);

    // 9) softmax + weighted sum + fc2 + residual
    stage_f<<<M1, 128>>>(feat, fc2_w, fc2_b, out);
}

// round 4
// speedup vs baseline: 1.1803x; 1.0614x over previous
#include <cuda_runtime.h>
#include <math.h>

#define NB 4
#define NPTS 4096
#define KNN 16
#define DPf 64
#define DMf 128
#define M1 (NB*NPTS)          /* 16384  */
#define M2 (M1*KNN)           /* 262144 */
#define EPSV 1e-8f
#define PITCH 132             /* smem row pitch (floats) for 128-wide tiles */

// ---------------- scratch (static device globals; no allocation) ----------------
__device__ float g_x [(size_t)M1*DMf];
__device__ float g_q [(size_t)M1*DMf];
__device__ float g_kf[(size_t)M1*DMf];
__device__ float g_vf[(size_t)M1*DMf];
__device__ int   g_idx[M1*KNN];
__device__ float g_sim[M2];
__device__ float g_bufA[(size_t)M2*DMf];   // h1 -> (fused) -> a (logits)
__device__ float g_bufB[(size_t)M2*DMf];   // qk
__device__ float g_pe  [(size_t)M2*DMf];   // pos_enc

// ---------------- packed f32x2 helpers ----------------
__device__ __forceinline__ unsigned long long pack2(float x, float y) {
    unsigned long long r;
    asm("mov.b64 %0, {%1, %2};" : "=l"(r) : "f"(x), "f"(y));
    return r;
}
__device__ __forceinline__ float2 unpack2(unsigned long long v) {
    float2 f;
    asm("mov.b64 {%0, %1}, %2;" : "=f"(f.x), "=f"(f.y) : "l"(v));
    return f;
}
__device__ __forceinline__ void ffma2(unsigned long long& d,
                                      unsigned long long a,
                                      unsigned long long b) {
    asm("fma.rn.f32x2 %0, %1, %2, %0;" : "+l"(d) : "l"(a), "l"(b));
}

// ---------------- cp.async helpers ----------------
__device__ __forceinline__ unsigned smem_u32(const void* p) {
    unsigned a;
    asm("{ .reg .u64 t; cvta.to.shared.u64 t, %1; cvt.u32.u64 %0, t; }" : "=r"(a) : "l"(p));
    return a;
}
__device__ __forceinline__ void cpa16(unsigned dst, const void* src) {
    asm volatile("cp.async.ca.shared.global [%0], [%1], 16;" :: "r"(dst), "l"(src));
}
__device__ __forceinline__ void cpa_commit() { asm volatile("cp.async.commit_group;"); }
template<int N> __device__ __forceinline__ void cpa_wait() {
    asm volatile("cp.async.wait_group %0;" :: "n"(N));
}

// ---------------- KNN: warp per query, stable (dist,idx) top-16 ----------------
__global__ void knn_kernel(const float* __restrict__ xyz) {
    int warp = threadIdx.x >> 5;
    int lane = threadIdx.x & 31;
    int row  = blockIdx.x * 4 + warp;
    int b = row >> 12;
    int n = row & (NPTS - 1);
    const float* xb = xyz + (size_t)b * NPTS * 3;
    float qx = xb[n*3+0], qy = xb[n*3+1], qz = xb[n*3+2];
    float sq = qx*qx + qy*qy + qz*qz;

    unsigned long long best[16];
#pragma unroll
    for (int i = 0; i < 16; i++) best[i] = ~0ULL;

    for (int t = 0; t < NPTS/32; t++) {
        int j = t*32 + lane;
        float x = xb[j*3+0], y = xb[j*3+1], z = xb[j*3+2];
        float sj = x*x + y*y + z*z;
        float d = sq + sj - 2.0f*(qx*x + qy*y + qz*z);
        unsigned u = __float_as_uint(d);
        u = (u & 0x80000000u) ? ~u : (u | 0x80000000u);
        unsigned long long key = ((unsigned long long)u << 32) | (unsigned)j;
        if (key < best[15]) {
            int p = 15;
            while (p > 0 && best[p-1] > key) { best[p] = best[p-1]; p--; }
            best[p] = key;
        }
    }

    __shared__ unsigned long long sh[4][512];
#pragma unroll
    for (int i = 0; i < 16; i++) sh[warp][lane*16 + i] = best[i];
    __syncwarp();

    int p = 0;
    for (int r = 0; r < 16; r++) {
        unsigned long long v = (p < 16) ? sh[warp][lane*16 + p] : ~0ULL;
        unsigned long long m = v;
#pragma unroll
        for (int off = 16; off; off >>= 1) {
            unsigned long long o = __shfl_xor_sync(0xffffffffu, m, off);
            m = (o < m) ? o : m;
        }
        if (v == m) { g_idx[row*KNN + r] = (int)(m & 0xffffffffu); p++; }
        __syncwarp();
    }
}

// ---------------- small fp32 GEMM (fc1, qkv): C[M x 128] = A[M x Ka] @ W ----------------
__global__ void __launch_bounds__(256, 2)
gemm_small(const float* __restrict__ A, int lda, int Ka,
           const float* __restrict__ W,
           const float* __restrict__ bias,
           float* __restrict__ C,
           const float* W2, float* C2, const float* W3, float* C3) {
    __shared__ float As[32][132];
    __shared__ float Ws[32][128];

    if (gridDim.y == 3) {
        if (blockIdx.y == 1) { W = W2; C = C2; }
        else if (blockIdx.y == 2) { W = W3; C = C3; }
    }

    int bm  = blockIdx.x * 128;
    int tid = threadIdx.x;
    int tm  = tid >> 4, tn = tid & 15;

    unsigned long long acc[8][4];
#pragma unroll
    for (int i = 0; i < 8; i++)
#pragma unroll
        for (int j = 0; j < 4; j++) acc[i][j] = 0ULL;

    for (int k0 = 0; k0 < Ka; k0 += 32) {
#pragma unroll
        for (int pss = 0; pss < 4; pss++) {
            int idx4 = pss*256 + tid;
            int r  = idx4 >> 3;
            int c4 = idx4 & 7;
            float4 v = *(const float4*)(A + (size_t)(bm + r)*lda + k0 + c4*4);
            As[c4*4+0][r] = v.x; As[c4*4+1][r] = v.y;
            As[c4*4+2][r] = v.z; As[c4*4+3][r] = v.w;
        }
#pragma unroll
        for (int pss = 0; pss < 4; pss++) {
            int idx4 = pss*256 + tid;
            int r  = idx4 >> 5;
            int c4 = idx4 & 31;
            *(float4*)&Ws[r][c4*4] = *(const float4*)(W + (size_t)(k0 + r)*128 + c4*4);
        }
        __syncthreads();
#pragma unroll
        for (int kk = 0; kk < 32; kk++) {
            float4 a0 = *(const float4*)&As[kk][tm*8];
            float4 a1 = *(const float4*)&As[kk][tm*8 + 4];
            float4 b0 = *(const float4*)&Ws[kk][tn*8];
            float4 b1 = *(const float4*)&Ws[kk][tn*8 + 4];
            unsigned long long bv[4] = { pack2(b0.x, b0.y), pack2(b0.z, b0.w),
                                         pack2(b1.x, b1.y), pack2(b1.z, b1.w) };
            unsigned long long av[8] = { pack2(a0.x, a0.x), pack2(a0.y, a0.y),
                                         pack2(a0.z, a0.z), pack2(a0.w, a0.w),
                                         pack2(a1.x, a1.x), pack2(a1.y, a1.y),
                                         pack2(a1.z, a1.z), pack2(a1.w, a1.w) };
#pragma unroll
            for (int i = 0; i < 8; i++)
#pragma unroll
                for (int j = 0; j < 4; j++) ffma2(acc[i][j], av[i], bv[j]);
        }
        __syncthreads();
    }

    float bia[8];
#pragma unroll
    for (int j = 0; j < 8; j++) bia[j] = bias ? bias[tn*8 + j] : 0.0f;

#pragma unroll
    for (int i = 0; i < 8; i++) {
        size_t row = (size_t)bm + tm*8 + i;
        float v[8];
#pragma unroll
        for (int j = 0; j < 4; j++) {
            float2 f = unpack2(acc[i][j]);
            v[2*j]   = f.x + bia[2*j];
            v[2*j+1] = f.y + bia[2*j+1];
        }
        float4* cp = (float4*)(C + row*128 + tn*8);
        cp[0] = make_float4(v[0], v[1], v[2], v[3]);
        cp[1] = make_float4(v[4], v[5], v[6], v[7]);
    }
}

// ---------------- fused chain: pe = h1@d2+b; t = pe + qk@simw' + sim*sw0 + sim_b;
//                  h2 = relu(t@g1+b); a = h2@g2+b ----------------
// Per CTA: one 128-row block.  Microtile 8 rows x (cols tn*4..+3, 64+tn*4..+3).
__device__ __forceinline__ void gemm_inner128(const float* __restrict__ Asm,
                                              const float* __restrict__ Wsm,
                                              int tm, int tn,
                                              unsigned long long acc[8][4]) {
    int arow = tm*8;
#pragma unroll 4
    for (int kk = 0; kk < 128; kk++) {
        float4 b0 = *(const float4*)&Wsm[kk*128 + tn*4];        // cols tn*4..+3
        float4 b1 = *(const float4*)&Wsm[kk*128 + 64 + tn*4];   // cols 64+tn*4..+3
        unsigned long long bv[4] = { pack2(b0.x, b0.y), pack2(b0.z, b0.w),
                                     pack2(b1.x, b1.y), pack2(b1.z, b1.w) };
        float a[8];
#pragma unroll
        for (int i = 0; i < 8; i++) a[i] = Asm[(arow + i)*PITCH + kk];  // broadcast LDS
#pragma unroll
        for (int i = 0; i < 8; i++) {
            unsigned long long av = pack2(a[i], a[i]);
#pragma unroll
            for (int j = 0; j < 4; j++) ffma2(acc[i][j], av, bv[j]);
        }
    }
}

__device__ __forceinline__ void load_tile_async(unsigned sT, const float* __restrict__ G,
                                                size_t bm, int tid) {
    for (int c = tid; c < 4096; c += 256) {
        int r = c >> 5, k = c & 31;
        cpa16(sT + (unsigned)(r*PITCH + k*4)*4u, G + (bm + r)*128 + k*4);
    }
}
__device__ __forceinline__ void load_W_async(unsigned sW, const float* __restrict__ W, int tid) {
    for (int c = tid; c < 4096; c += 256)
        cpa16(sW + (unsigned)c*16u, W + c*4);
}

__global__ void __launch_bounds__(256, 1)
fused_chain(const float* __restrict__ d2_w, const float* __restrict__ d2_b,
            const float* __restrict__ sim_w, const float* __restrict__ sim_b,
            const float* __restrict__ g1_w, const float* __restrict__ g1_b,
            const float* __restrict__ g2_w, const float* __restrict__ g2_b) {
    extern __shared__ float sm[];
    float* As = sm;                       // 128 x PITCH
    float* Bs = sm + 128*PITCH;           // 128 x PITCH
    float* Ws = sm + 2*128*PITCH;         // 128 x 128
    unsigned sAs = smem_u32(As), sBs = smem_u32(Bs), sWs = smem_u32(Ws);

    int tid = threadIdx.x;
    int tm = tid >> 4, tn = tid & 15;
    size_t bm = (size_t)blockIdx.x * 128;

    // async: group0 = {h1->As, d2_w->Ws}, group1 = {qk->Bs}
    load_tile_async(sAs, g_bufA, bm, tid);
    load_W_async(sWs, d2_w, tid);
    cpa_commit();
    load_tile_async(sBs, g_bufB, bm, tid);
    cpa_commit();
    cpa_wait<1>();
    __syncthreads();

    unsigned long long acc[8][4];
#pragma unroll
    for (int i = 0; i < 8; i++)
#pragma unroll
        for (int j = 0; j < 4; j++) acc[i][j] = 0ULL;

    // ---- GEMM1: acc = h1 @ d2 ----
    gemm_inner128(As, Ws, tm, tn, acc);

    // epi1: += d2_b; write pe
    {
        float4 b0 = *(const float4*)(d2_b + tn*4);
        float4 b1 = *(const float4*)(d2_b + 64 + tn*4);
        float bb[8] = {b0.x,b0.y,b0.z,b0.w,b1.x,b1.y,b1.z,b1.w};
#pragma unroll
        for (int i = 0; i < 8; i++) {
            size_t row = bm + tm*8 + i;
            float v[8];
#pragma unroll
            for (int j = 0; j < 4; j++) {
                float2 f = unpack2(acc[i][j]);
                v[2*j] = f.x + bb[2*j]; v[2*j+1] = f.y + bb[2*j+1];
                acc[i][j] = pack2(v[2*j], v[2*j+1]);
            }
            *(float4*)(g_pe + row*128 + tn*4)      = make_float4(v[0],v[1],v[2],v[3]);
            *(float4*)(g_pe + row*128 + 64 + tn*4) = make_float4(v[4],v[5],v[6],v[7]);
        }
    }
    __syncthreads();                       // all warps done reading Ws (d2_w)
    load_W_async(sWs, sim_w + 128, tid);   // rows 1..128 of sim_w
    cpa_commit();
    cpa_wait<0>();                         // also drains qk group
    __syncthreads();

    // ---- GEMM2: acc += qk @ simw' ----
    gemm_inner128(Bs, Ws, tm, tn, acc);

    // epi2: += sim_b + sim[row]*sim_w[0];  stage t -> As
    {
        float4 b0 = *(const float4*)(sim_b + tn*4);
        float4 b1 = *(const float4*)(sim_b + 64 + tn*4);
        float4 s0 = *(const float4*)(sim_w + tn*4);
        float4 s1 = *(const float4*)(sim_w + 64 + tn*4);
        float bb[8] = {b0.x,b0.y,b0.z,b0.w,b1.x,b1.y,b1.z,b1.w};
        float sw[8] = {s0.x,s0.y,s0.z,s0.w,s1.x,s1.y,s1.z,s1.w};
#pragma unroll
        for (int i = 0; i < 8; i++) {
            int r = tm*8 + i;
            float sv = g_sim[bm + r];
            float v[8];
#pragma unroll
            for (int j = 0; j < 4; j++) {
                float2 f = unpack2(acc[i][j]);
                v[2*j]   = f.x + bb[2*j]   + sv*sw[2*j];
                v[2*j+1] = f.y + bb[2*j+1] + sv*sw[2*j+1];
            }
            *(float4*)&As[r*PITCH + tn*4]      = make_float4(v[0],v[1],v[2],v[3]);
            *(float4*)&As[r*PITCH + 64 + tn*4] = make_float4(v[4],v[5],v[6],v[7]);
        }
    }
    __syncthreads();                       // t staged; Ws free
    load_W_async(sWs, g1_w, tid);
    cpa_commit();
    cpa_wait<0>();
    __syncthreads();

    // ---- GEMM3: acc = t @ g1 ----
#pragma unroll
    for (int i = 0; i < 8; i++)
#pragma unroll
        for (int j = 0; j < 4; j++) acc[i][j] = 0ULL;
    gemm_inner128(As, Ws, tm, tn, acc);

    // epi3: relu(+g1_b); stage h2 -> Bs
    {
        float4 b0 = *(const float4*)(g1_b + tn*4);
        float4 b1 = *(const float4*)(g1_b + 64 + tn*4);
        float bb[8] = {b0.x,b0.y,b0.z,b0.w,b1.x,b1.y,b1.z,b1.w};
#pragma unroll
        for (int i = 0; i < 8; i++) {
            int r = tm*8 + i;
            float v[8];
#pragma unroll
            for (int j = 0; j < 4; j++) {
                float2 f = unpack2(acc[i][j]);
                v[2*j]   = fmaxf(f.x + bb[2*j],   0.0f);
                v[2*j+1] = fmaxf(f.y + bb[2*j+1], 0.0f);
            }
            *(float4*)&Bs[r*PITCH + tn*4]      = make_float4(v[0],v[1],v[2],v[3]);
            *(float4*)&Bs[r*PITCH + 64 + tn*4] = make_float4(v[4],v[5],v[6],v[7]);
        }
    }
    __syncthreads();
    load_W_async(sWs, g2_w, tid);
    cpa_commit();
    cpa_wait<0>();
    __syncthreads();

    // ---- GEMM4: acc = h2 @ g2 ----
#pragma unroll
    for (int i = 0; i < 8; i++)
#pragma unroll
        for (int j = 0; j < 4; j++) acc[i][j] = 0ULL;
    gemm_inner128(Bs, Ws, tm, tn, acc);

    // epi4: += g2_b; write logits a -> g_bufA (our block's h1 fully consumed)
    {
        float4 b0 = *(const float4*)(g2_b + tn*4);
        float4 b1 = *(const float4*)(g2_b + 64 + tn*4);
        float bb[8] = {b0.x,b0.y,b0.z,b0.w,b1.x,b1.y,b1.z,b1.w};
#pragma unroll
        for (int i = 0; i < 8; i++) {
            size_t row = bm + tm*8 + i;
            float v[8];
#pragma unroll
            for (int j = 0; j < 4; j++) {
                float2 f = unpack2(acc[i][j]);
                v[2*j] = f.x + bb[2*j]; v[2*j+1] = f.y + bb[2*j+1];
            }
            *(float4*)(g_bufA + row*128 + tn*4)      = make_float4(v[0],v[1],v[2],v[3]);
            *(float4*)(g_bufA + row*128 + 64 + tn*4) = make_float4(v[4],v[5],v[6],v[7]);
        }
    }
}

// ---------------- stage D: warp per row, shfl reductions ----------------
__global__ void stage_d(const float* __restrict__ xyz,
                        const float* __restrict__ d1_w,
                        const float* __restrict__ d1_b) {
    int wid = threadIdx.x >> 5, lane = threadIdx.x & 31;
    int row = blockIdx.x * 8 + wid;          // [0, M1)
    int b = row >> 12;
    int n = row & (NPTS - 1);
    const float* xb = xyz + (size_t)b*NPTS*3;
    float qx = xb[n*3+0], qy = xb[n*3+1], qz = xb[n*3+2];

    float4 qf = *(const float4*)(g_q + (size_t)row*DMf + lane*4);
    float s = qf.x*qf.x + qf.y*qf.y + qf.z*qf.z + qf.w*qf.w;
#pragma unroll
    for (int off = 16; off; off >>= 1) s += __shfl_xor_sync(0xffffffffu, s, off);
    float qn = fmaxf(sqrtf(s), EPSV);

    float4 w0 = *(const float4*)(d1_w + lane*4);
    float4 w1 = *(const float4*)(d1_w + 128 + lane*4);
    float4 w2 = *(const float4*)(d1_w + 256 + lane*4);
    float4 db = *(const float4*)(d1_b + lane*4);

#pragma unroll 2
    for (int k = 0; k < KNN; k++) {
        int idx = g_idx[row*KNN + k];
        const float* kp = g_kf + ((size_t)(b*NPTS + idx))*DMf + lane*4;
        float4 kf = *(const float4*)kp;
        float dq = qf.x*kf.x + qf.y*kf.y + qf.z*kf.z + qf.w*kf.w;
        float dk = kf.x*kf.x + kf.y*kf.y + kf.z*kf.z + kf.w*kf.w;
#pragma unroll
        for (int off = 16; off; off >>= 1) {
            dq += __shfl_xor_sync(0xffffffffu, dq, off);
            dk += __shfl_xor_sync(0xffffffffu, dk, off);
        }
        float kn = fmaxf(sqrtf(dk), EPSV);
        float sim = dq / (qn * kn);
        if (lane == 0) g_sim[row*KNN + k] = sim;
        size_t orow = ((size_t)row*KNN + k)*DMf;
        *(float4*)(g_bufB + orow + lane*4) =
            make_float4(qf.x-kf.x, qf.y-kf.y, qf.z-kf.z, qf.w-kf.w);
        float cx = qx - xb[idx*3+0];
        float cy = qy - xb[idx*3+1];
        float cz = qz - xb[idx*3+2];
        float4 h;
        h.x = fmaxf(cx*w0.x + cy*w1.x + cz*w2.x + db.x, 0.0f);
        h.y = fmaxf(cx*w0.y + cy*w1.y + cz*w2.y + db.y, 0.0f);
        h.z = fmaxf(cx*w0.z + cy*w1.z + cz*w2.z + db.z, 0.0f);
        h.w = fmaxf(cx*w0.w + cy*w1.w + cz*w2.w + db.w, 0.0f);
        *(float4*)(g_bufA + orow + lane*4) = h;
    }
}

// ---------------- stage F: softmax + weighted sum + fc2 + residual ----------------
__global__ void stage_f(const float* __restrict__ features,
                        const float* __restrict__ fc2_w,
                        const float* __restrict__ fc2_b,
                        float* __restrict__ out) {
    int row = blockIdx.x;
    int f = threadIdx.x;
    int b = row >> 12;
    const float scale = 1.0f / sqrtf(128.0f);

    float a[KNN];
    float mx = -3.4e38f;
#pragma unroll
    for (int k = 0; k < KNN; k++) {
        a[k] = g_bufA[((size_t)row*KNN + k)*DMf + f] * scale;
        mx = fmaxf(mx, a[k]);
    }
    float sum = 0.0f;
#pragma unroll
    for (int k = 0; k < KNN; k++) { a[k] = expf(a[k] - mx); sum += a[k]; }
    float inv = 1.0f / sum;

    float* out_attn = out + (size_t)M1*DPf;
    float r = 0.0f;
#pragma unroll
    for (int k = 0; k < KNN; k++) {
        float at = a[k] * inv;
        size_t orow = ((size_t)row*KNN + k)*DMf;
        out_attn[orow + f] = at;
        int idx = g_idx[row*KNN + k];
        float v = g_vf[((size_t)(b*NPTS + idx))*DMf + f] + g_pe[orow + f];
        r += at * v;
    }
    __shared__ float rs[DMf];
    rs[f] = r;
    __syncthreads();
    if (f < DPf) {
        float o = fc2_b[f];
#pragma unroll 8
        for (int j = 0; j < DMf; j++) o += rs[j] * fc2_w[j*DPf + f];
        o += features[(size_t)row*DPf + f];
        out[(size_t)row*DPf + f] = o;
    }
}

// ---------------- launch ----------------
extern "C" void kernel_launch(void* const* d_in, const int* in_sizes, int n_in,
                              void* d_out, int out_size) {
    const float* xyz   = (const float*)d_in[0];
    const float* feat  = (const float*)d_in[1];
    const float* fc1_w = (const float*)d_in[2];
    const float* fc1_b = (const float*)d_in[3];
    const float* fc2_w = (const float*)d_in[4];
    const float* fc2_b = (const float*)d_in[5];
    const float* d1_w  = (const float*)d_in[6];
    const float* d1_b  = (const float*)d_in[7];
    const float* d2_w  = (const float*)d_in[8];
    const float* d2_b  = (const float*)d_in[9];
    const float* g1_w  = (const float*)d_in[10];
    const float* g1_b  = (const float*)d_in[11];
    const float* g2_w  = (const float*)d_in[12];
    const float* g2_b  = (const float*)d_in[13];
    const float* wq_w  = (const float*)d_in[14];
    const float* wk_w  = (const float*)d_in[15];
    const float* wv_w  = (const float*)d_in[16];
    const float* sim_w = (const float*)d_in[17];
    const float* sim_b = (const float*)d_in[18];
    float* out = (float*)d_out;

    static float *p_x = nullptr, *p_q, *p_kf, *p_vf;
    static bool attr_done = false;
    const int FUSED_SMEM = (2*128*PITCH + 128*128) * 4;   // 200704 B
    if (!attr_done) {
        cudaGetSymbolAddress((void**)&p_x,  g_x);
        cudaGetSymbolAddress((void**)&p_q,  g_q);
        cudaGetSymbolAddress((void**)&p_kf, g_kf);
        cudaGetSymbolAddress((void**)&p_vf, g_vf);
        cudaFuncSetAttribute(fused_chain,
                             cudaFuncAttributeMaxDynamicSharedMemorySize, FUSED_SMEM);
        attr_done = true;
    }

    // 1) KNN
    knn_kernel<<<M1/4, 128>>>(xyz);

    // 2) x = features @ fc1 + b
    gemm_small<<<M1/128, 256>>>(feat, DPf, DPf, fc1_w, fc1_b, p_x,
                                nullptr, nullptr, nullptr, nullptr);

    // 3) q, k, v (batched)
    gemm_small<<<dim3(M1/128, 3), 256>>>(p_x, DMf, DMf, wq_w, nullptr, p_q,
                                         wk_w, p_kf, wv_w, p_vf);

    // 4) gather + sim + (q-k)->bufB + pos-enc hidden->bufA
    stage_d<<<M1/8, 256>>>(xyz, d1_w, d1_b);

    // 5-8) fused: pe + t + h2 + a  (a -> g_bufA, pe -> g_pe)
    fused_chain<<<M2/128, 256, FUSED_SMEM>>>(d2_w, d2_b, sim_w, sim_b,
                                             g1_w, g1_b, g2_w, g2_b);

    // 9) softmax + weighted sum + fc2 + residual
    stage_f<<<M1, 128>>>(feat, fc2_w, fc2_b, out);
}

// round 5
// speedup vs baseline: 1.1899x; 1.0081x over previous
#include <cuda_runtime.h>
#include <math.h>

#define NB 4
#define NPTS 4096
#define KNN 16
#define DPf 64
#define DMf 128
#define M1 (NB*NPTS)          /* 16384  */
#define M2 (M1*KNN)           /* 262144 */
#define EPSV 1e-8f
#define PITCH 132             /* smem row pitch (floats); row stride 4*132=528, 528%32=16 -> conflict-free */
#define BROWS 64              /* rows per fused CTA */

// ---------------- scratch (static device globals; no allocation) ----------------
__device__ float g_x [(size_t)M1*DMf];
__device__ float g_q [(size_t)M1*DMf];
__device__ float g_kf[(size_t)M1*DMf];
__device__ float g_vf[(size_t)M1*DMf];
__device__ int   g_idx[M1*KNN];
__device__ float g_sim[M2];
__device__ float g_bufA[(size_t)M2*DMf];   // h1 -> (fused) -> a (logits)
__device__ float g_bufB[(size_t)M2*DMf];   // qk
__device__ float g_pe  [(size_t)M2*DMf];   // pos_enc

// ---------------- packed f32x2 helpers ----------------
__device__ __forceinline__ unsigned long long pack2(float x, float y) {
    unsigned long long r;
    asm("mov.b64 %0, {%1, %2};" : "=l"(r) : "f"(x), "f"(y));
    return r;
}
__device__ __forceinline__ float2 unpack2(unsigned long long v) {
    float2 f;
    asm("mov.b64 {%0, %1}, %2;" : "=f"(f.x), "=f"(f.y) : "l"(v));
    return f;
}
__device__ __forceinline__ void ffma2(unsigned long long& d,
                                      unsigned long long a,
                                      unsigned long long b) {
    asm("fma.rn.f32x2 %0, %1, %2, %0;" : "+l"(d) : "l"(a), "l"(b));
}

// ---------------- cp.async helpers ----------------
__device__ __forceinline__ unsigned smem_u32(const void* p) {
    unsigned a;
    asm("{ .reg .u64 t; cvta.to.shared.u64 t, %1; cvt.u32.u64 %0, t; }" : "=r"(a) : "l"(p));
    return a;
}
__device__ __forceinline__ void cpa16(unsigned dst, const void* src) {
    asm volatile("cp.async.ca.shared.global [%0], [%1], 16;" :: "r"(dst), "l"(src));
}
__device__ __forceinline__ void cpa_commit() { asm volatile("cp.async.commit_group;"); }
template<int N> __device__ __forceinline__ void cpa_wait() {
    asm volatile("cp.async.wait_group %0;" :: "n"(N));
}

// ---------------- KNN: warp per query, stable (dist,idx) top-16 ----------------
__global__ void knn_kernel(const float* __restrict__ xyz) {
    int warp = threadIdx.x >> 5;
    int lane = threadIdx.x & 31;
    int row  = blockIdx.x * 4 + warp;
    int b = row >> 12;
    int n = row & (NPTS - 1);
    const float* xb = xyz + (size_t)b * NPTS * 3;
    float qx = xb[n*3+0], qy = xb[n*3+1], qz = xb[n*3+2];
    float sq = qx*qx + qy*qy + qz*qz;

    unsigned long long best[16];
#pragma unroll
    for (int i = 0; i < 16; i++) best[i] = ~0ULL;

    for (int t = 0; t < NPTS/32; t++) {
        int j = t*32 + lane;
        float x = xb[j*3+0], y = xb[j*3+1], z = xb[j*3+2];
        float sj = x*x + y*y + z*z;
        float d = sq + sj - 2.0f*(qx*x + qy*y + qz*z);
        unsigned u = __float_as_uint(d);
        u = (u & 0x80000000u) ? ~u : (u | 0x80000000u);
        unsigned long long key = ((unsigned long long)u << 32) | (unsigned)j;
        if (key < best[15]) {
            int p = 15;
            while (p > 0 && best[p-1] > key) { best[p] = best[p-1]; p--; }
            best[p] = key;
        }
    }

    __shared__ unsigned long long sh[4][512];
#pragma unroll
    for (int i = 0; i < 16; i++) sh[warp][lane*16 + i] = best[i];
    __syncwarp();

    int p = 0;
    for (int r = 0; r < 16; r++) {
        unsigned long long v = (p < 16) ? sh[warp][lane*16 + p] : ~0ULL;
        unsigned long long m = v;
#pragma unroll
        for (int off = 16; off; off >>= 1) {
            unsigned long long o = __shfl_xor_sync(0xffffffffu, m, off);
            m = (o < m) ? o : m;
        }
        if (v == m) { g_idx[row*KNN + r] = (int)(m & 0xffffffffu); p++; }
        __syncwarp();
    }
}

// ---------------- small fp32 GEMM (fc1, qkv): C[M x 128] = A[M x Ka] @ W ----------------
__global__ void __launch_bounds__(256, 2)
gemm_small(const float* __restrict__ A, int lda, int Ka,
           const float* __restrict__ W,
           const float* __restrict__ bias,
           float* __restrict__ C,
           const float* W2, float* C2, const float* W3, float* C3) {
    __shared__ float As[32][132];
    __shared__ float Ws[32][128];

    if (gridDim.y == 3) {
        if (blockIdx.y == 1) { W = W2; C = C2; }
        else if (blockIdx.y == 2) { W = W3; C = C3; }
    }

    int bm  = blockIdx.x * 128;
    int tid = threadIdx.x;
    int tm  = tid >> 4, tn = tid & 15;

    unsigned long long acc[8][4];
#pragma unroll
    for (int i = 0; i < 8; i++)
#pragma unroll
        for (int j = 0; j < 4; j++) acc[i][j] = 0ULL;

    for (int k0 = 0; k0 < Ka; k0 += 32) {
#pragma unroll
        for (int pss = 0; pss < 4; pss++) {
            int idx4 = pss*256 + tid;
            int r  = idx4 >> 3;
            int c4 = idx4 & 7;
            float4 v = *(const float4*)(A + (size_t)(bm + r)*lda + k0 + c4*4);
            As[c4*4+0][r] = v.x; As[c4*4+1][r] = v.y;
            As[c4*4+2][r] = v.z; As[c4*4+3][r] = v.w;
        }
#pragma unroll
        for (int pss = 0; pss < 4; pss++) {
            int idx4 = pss*256 + tid;
            int r  = idx4 >> 5;
            int c4 = idx4 & 31;
            *(float4*)&Ws[r][c4*4] = *(const float4*)(W + (size_t)(k0 + r)*128 + c4*4);
        }
        __syncthreads();
#pragma unroll
        for (int kk = 0; kk < 32; kk++) {
            float4 a0 = *(const float4*)&As[kk][tm*8];
            float4 a1 = *(const float4*)&As[kk][tm*8 + 4];
            float4 b0 = *(const float4*)&Ws[kk][tn*8];
            float4 b1 = *(const float4*)&Ws[kk][tn*8 + 4];
            unsigned long long bv[4] = { pack2(b0.x, b0.y), pack2(b0.z, b0.w),
                                         pack2(b1.x, b1.y), pack2(b1.z, b1.w) };
            unsigned long long av[8] = { pack2(a0.x, a0.x), pack2(a0.y, a0.y),
                                         pack2(a0.z, a0.z), pack2(a0.w, a0.w),
                                         pack2(a1.x, a1.x), pack2(a1.y, a1.y),
                                         pack2(a1.z, a1.z), pack2(a1.w, a1.w) };
#pragma unroll
            for (int i = 0; i < 8; i++)
#pragma unroll
                for (int j = 0; j < 4; j++) ffma2(acc[i][j], av[i], bv[j]);
        }
        __syncthreads();
    }

    float bia[8];
#pragma unroll
    for (int j = 0; j < 8; j++) bia[j] = bias ? bias[tn*8 + j] : 0.0f;

#pragma unroll
    for (int i = 0; i < 8; i++) {
        size_t row = (size_t)bm + tm*8 + i;
        float v[8];
#pragma unroll
        for (int j = 0; j < 4; j++) {
            float2 f = unpack2(acc[i][j]);
            v[2*j]   = f.x + bia[2*j];
            v[2*j+1] = f.y + bia[2*j+1];
        }
        float4* cp = (float4*)(C + row*128 + tn*8);
        cp[0] = make_float4(v[0], v[1], v[2], v[3]);
        cp[1] = make_float4(v[4], v[5], v[6], v[7]);
    }
}

// ---------------- fused chain (v2): 64-row blocks, 2 CTAs/SM, K-halved weights ----------------
// pe = h1@d2+b; t = pe + qk@simw' + sim*sw0 + sim_b; h2 = relu(t@g1+b); a = h2@g2+b
// Microtile: 4 rows x 8 cols (cols tn*4..+3 and 64+tn*4..+3).
__device__ __forceinline__ void gemm_inner64(const float* __restrict__ Asm, int kbase,
                                             const float* __restrict__ Wsm,
                                             int tm, int tn,
                                             unsigned long long acc[4][4]) {
    const float* ap = Asm + tm*4*PITCH + kbase;
#pragma unroll 8
    for (int kk = 0; kk < 64; kk++) {
        float4 b0 = *(const float4*)&Wsm[kk*128 + tn*4];
        float4 b1 = *(const float4*)&Wsm[kk*128 + 64 + tn*4];
        unsigned long long bv[4] = { pack2(b0.x, b0.y), pack2(b0.z, b0.w),
                                     pack2(b1.x, b1.y), pack2(b1.z, b1.w) };
#pragma unroll
        for (int i = 0; i < 4; i++) {
            float a = ap[i*PITCH + kk];
            unsigned long long av = pack2(a, a);
#pragma unroll
            for (int j = 0; j < 4; j++) ffma2(acc[i][j], av, bv[j]);
        }
    }
}

// load 64x128 tile (row-major, pitch PITCH) from global
__device__ __forceinline__ void load_tile_async(unsigned sT, const float* __restrict__ G,
                                                size_t bm, int tid) {
#pragma unroll
    for (int it = 0; it < 8; it++) {
        int c = it*256 + tid;             // 2048 float4 chunks
        int r = c >> 5, k = c & 31;
        cpa16(sT + (unsigned)(r*PITCH + k*4)*4u, G + (bm + r)*128 + k*4);
    }
}
// load 64x128 weight half (rows h*64..) densely
__device__ __forceinline__ void load_W_half(unsigned sW, const float* __restrict__ W, int h, int tid) {
    const float* src = W + (size_t)h*64*128;
#pragma unroll
    for (int it = 0; it < 8; it++) {
        int c = it*256 + tid;
        cpa16(sW + (unsigned)c*16u, src + c*4);
    }
}

__global__ void __launch_bounds__(256, 2)
fused_chain(const float* __restrict__ d2_w, const float* __restrict__ d2_b,
            const float* __restrict__ sim_w, const float* __restrict__ sim_b,
            const float* __restrict__ g1_w, const float* __restrict__ g1_b,
            const float* __restrict__ g2_w, const float* __restrict__ g2_b) {
    extern __shared__ float sm[];
    float* As = sm;                         // 64 x PITCH  (h1, later t)
    float* Bs = sm + BROWS*PITCH;           // 64 x PITCH  (qk, later h2)
    float* Ws = sm + 2*BROWS*PITCH;         // 64 x 128    (weight half)
    unsigned sAs = smem_u32(As), sBs = smem_u32(Bs), sWs = smem_u32(Ws);

    int tid = threadIdx.x;
    int tm = tid >> 4, tn = tid & 15;       // tm: 16 groups of 4 rows; tn: 16 col groups
    size_t bm = (size_t)blockIdx.x * BROWS;

    // group0 = {h1->As, Ws=d2_w half0}; group1 = {qk->Bs}
    load_tile_async(sAs, g_bufA, bm, tid);
    load_W_half(sWs, d2_w, 0, tid);
    cpa_commit();
    load_tile_async(sBs, g_bufB, bm, tid);
    cpa_commit();
    cpa_wait<1>();
    __syncthreads();

    unsigned long long acc[4][4];
#pragma unroll
    for (int i = 0; i < 4; i++)
#pragma unroll
        for (int j = 0; j < 4; j++) acc[i][j] = 0ULL;

#define RELOAD_W(Wp, h)  do { __syncthreads(); load_W_half(sWs, (Wp), (h), tid); \
                              cpa_commit(); cpa_wait<0>(); __syncthreads(); } while (0)

    // ---- GEMM1: acc = h1 @ d2 ----
    gemm_inner64(As, 0, Ws, tm, tn, acc);
    RELOAD_W(d2_w, 1);
    gemm_inner64(As, 64, Ws, tm, tn, acc);

    // epi1: += d2_b; write pe; keep acc
    {
        float4 b0 = *(const float4*)(d2_b + tn*4);
        float4 b1 = *(const float4*)(d2_b + 64 + tn*4);
        float bb[8] = {b0.x,b0.y,b0.z,b0.w,b1.x,b1.y,b1.z,b1.w};
#pragma unroll
        for (int i = 0; i < 4; i++) {
            size_t row = bm + tm*4 + i;
            float v[8];
#pragma unroll
            for (int j = 0; j < 4; j++) {
                float2 f = unpack2(acc[i][j]);
                v[2*j] = f.x + bb[2*j]; v[2*j+1] = f.y + bb[2*j+1];
                acc[i][j] = pack2(v[2*j], v[2*j+1]);
            }
            *(float4*)(g_pe + row*128 + tn*4)      = make_float4(v[0],v[1],v[2],v[3]);
            *(float4*)(g_pe + row*128 + 64 + tn*4) = make_float4(v[4],v[5],v[6],v[7]);
        }
    }

    // ---- GEMM2: acc += qk @ simw' ----
    RELOAD_W(sim_w + 128, 0);
    gemm_inner64(Bs, 0, Ws, tm, tn, acc);
    RELOAD_W(sim_w + 128, 1);
    gemm_inner64(Bs, 64, Ws, tm, tn, acc);

    // epi2: += sim_b + sim[row]*sim_w[0]; stage t -> As
    {
        float4 b0 = *(const float4*)(sim_b + tn*4);
        float4 b1 = *(const float4*)(sim_b + 64 + tn*4);
        float4 s0 = *(const float4*)(sim_w + tn*4);
        float4 s1 = *(const float4*)(sim_w + 64 + tn*4);
        float bb[8] = {b0.x,b0.y,b0.z,b0.w,b1.x,b1.y,b1.z,b1.w};
        float sw[8] = {s0.x,s0.y,s0.z,s0.w,s1.x,s1.y,s1.z,s1.w};
#pragma unroll
        for (int i = 0; i < 4; i++) {
            int r = tm*4 + i;
            float sv = g_sim[bm + r];
            float v[8];
#pragma unroll
            for (int j = 0; j < 4; j++) {
                float2 f = unpack2(acc[i][j]);
                v[2*j]   = f.x + bb[2*j]   + sv*sw[2*j];
                v[2*j+1] = f.y + bb[2*j+1] + sv*sw[2*j+1];
            }
            *(float4*)&As[r*PITCH + tn*4]      = make_float4(v[0],v[1],v[2],v[3]);
            *(float4*)&As[r*PITCH + 64 + tn*4] = make_float4(v[4],v[5],v[6],v[7]);
        }
    }

    // ---- GEMM3: acc = t @ g1 ----
#pragma unroll
    for (int i = 0; i < 4; i++)
#pragma unroll
        for (int j = 0; j < 4; j++) acc[i][j] = 0ULL;
    RELOAD_W(g1_w, 0);
    gemm_inner64(As, 0, Ws, tm, tn, acc);
    RELOAD_W(g1_w, 1);
    gemm_inner64(As, 64, Ws, tm, tn, acc);

    // epi3: relu(+g1_b); stage h2 -> Bs
    {
        float4 b0 = *(const float4*)(g1_b + tn*4);
        float4 b1 = *(const float4*)(g1_b + 64 + tn*4);
        float bb[8] = {b0.x,b0.y,b0.z,b0.w,b1.x,b1.y,b1.z,b1.w};
#pragma unroll
        for (int i = 0; i < 4; i++) {
            int r = tm*4 + i;
            float v[8];
#pragma unroll
            for (int j = 0; j < 4; j++) {
                float2 f = unpack2(acc[i][j]);
                v[2*j]   = fmaxf(f.x + bb[2*j],   0.0f);
                v[2*j+1] = fmaxf(f.y + bb[2*j+1], 0.0f);
            }
            *(float4*)&Bs[r*PITCH + tn*4]      = make_float4(v[0],v[1],v[2],v[3]);
            *(float4*)&Bs[r*PITCH + 64 + tn*4] = make_float4(v[4],v[5],v[6],v[7]);
        }
    }

    // ---- GEMM4: acc = h2 @ g2 ----
#pragma unroll
    for (int i = 0; i < 4; i++)
#pragma unroll
        for (int j = 0; j < 4; j++) acc[i][j] = 0ULL;
    RELOAD_W(g2_w, 0);
    gemm_inner64(Bs, 0, Ws, tm, tn, acc);
    RELOAD_W(g2_w, 1);
    gemm_inner64(Bs, 64, Ws, tm, tn, acc);

    // epi4: += g2_b; write logits -> g_bufA
    {
        float4 b0 = *(const float4*)(g2_b + tn*4);
        float4 b1 = *(const float4*)(g2_b + 64 + tn*4);
        float bb[8] = {b0.x,b0.y,b0.z,b0.w,b1.x,b1.y,b1.z,b1.w};
#pragma unroll
        for (int i = 0; i < 4; i++) {
            size_t row = bm + tm*4 + i;
            float v[8];
#pragma unroll
            for (int j = 0; j < 4; j++) {
                float2 f = unpack2(acc[i][j]);
                v[2*j] = f.x + bb[2*j]; v[2*j+1] = f.y + bb[2*j+1];
            }
            *(float4*)(g_bufA + row*128 + tn*4)      = make_float4(v[0],v[1],v[2],v[3]);
            *(float4*)(g_bufA + row*128 + 64 + tn*4) = make_float4(v[4],v[5],v[6],v[7]);
        }
    }
#undef RELOAD_W
}

// ---------------- stage D: warp per row, shfl reductions ----------------
__global__ void stage_d(const float* __restrict__ xyz,
                        const float* __restrict__ d1_w,
                        const float* __restrict__ d1_b) {
    int wid = threadIdx.x >> 5, lane = threadIdx.x & 31;
    int row = blockIdx.x * 8 + wid;
    int b = row >> 12;
    int n = row & (NPTS - 1);
    const float* xb = xyz + (size_t)b*NPTS*3;
    float qx = xb[n*3+0], qy = xb[n*3+1], qz = xb[n*3+2];

    float4 qf = *(const float4*)(g_q + (size_t)row*DMf + lane*4);
    float s = qf.x*qf.x + qf.y*qf.y + qf.z*qf.z + qf.w*qf.w;
#pragma unroll
    for (int off = 16; off; off >>= 1) s += __shfl_xor_sync(0xffffffffu, s, off);
    float qn = fmaxf(sqrtf(s), EPSV);

    float4 w0 = *(const float4*)(d1_w + lane*4);
    float4 w1 = *(const float4*)(d1_w + 128 + lane*4);
    float4 w2 = *(const float4*)(d1_w + 256 + lane*4);
    float4 db = *(const float4*)(d1_b + lane*4);

#pragma unroll 2
    for (int k = 0; k < KNN; k++) {
        int idx = g_idx[row*KNN + k];
        const float* kp = g_kf + ((size_t)(b*NPTS + idx))*DMf + lane*4;
        float4 kf = *(const float4*)kp;
        float dq = qf.x*kf.x + qf.y*kf.y + qf.z*kf.z + qf.w*kf.w;
        float dk = kf.x*kf.x + kf.y*kf.y + kf.z*kf.z + kf.w*kf.w;
#pragma unroll
        for (int off = 16; off; off >>= 1) {
            dq += __shfl_xor_sync(0xffffffffu, dq, off);
            dk += __shfl_xor_sync(0xffffffffu, dk, off);
        }
        float kn = fmaxf(sqrtf(dk), EPSV);
        float sim = dq / (qn * kn);
        if (lane == 0) g_sim[row*KNN + k] = sim;
        size_t orow = ((size_t)row*KNN + k)*DMf;
        *(float4*)(g_bufB + orow + lane*4) =
            make_float4(qf.x-kf.x, qf.y-kf.y, qf.z-kf.z, qf.w-kf.w);
        float cx = qx - xb[idx*3+0];
        float cy = qy - xb[idx*3+1];
        float cz = qz - xb[idx*3+2];
        float4 h;
        h.x = fmaxf(cx*w0.x + cy*w1.x + cz*w2.x + db.x, 0.0f);
        h.y = fmaxf(cx*w0.y + cy*w1.y + cz*w2.y + db.y, 0.0f);
        h.z = fmaxf(cx*w0.z + cy*w1.z + cz*w2.z + db.z, 0.0f);
        h.w = fmaxf(cx*w0.w + cy*w1.w + cz*w2.w + db.w, 0.0f);
        *(float4*)(g_bufA + orow + lane*4) = h;
    }
}

// ---------------- stage F: softmax + weighted sum + fc2 + residual ----------------
__global__ void stage_f(const float* __restrict__ features,
                        const float* __restrict__ fc2_w,
                        const float* __restrict__ fc2_b,
                        float* __restrict__ out) {
    int row = blockIdx.x;
    int f = threadIdx.x;
    int b = row >> 12;
    const float scale = 1.0f / sqrtf(128.0f);

    float a[KNN];
    float mx = -3.4e38f;
#pragma unroll
    for (int k = 0; k < KNN; k++) {
        a[k] = g_bufA[((size_t)row*KNN + k)*DMf + f] * scale;
        mx = fmaxf(mx, a[k]);
    }
    float sum = 0.0f;
#pragma unroll
    for (int k = 0; k < KNN; k++) { a[k] = expf(a[k] - mx); sum += a[k]; }
    float inv = 1.0f / sum;

    float* out_attn = out + (size_t)M1*DPf;
    float r = 0.0f;
#pragma unroll
    for (int k = 0; k < KNN; k++) {
        float at = a[k] * inv;
        size_t orow = ((size_t)row*KNN + k)*DMf;
        out_attn[orow + f] = at;
        int idx = g_idx[row*KNN + k];
        float v = g_vf[((size_t)(b*NPTS + idx))*DMf + f] + g_pe[orow + f];
        r += at * v;
    }
    __shared__ float rs[DMf];
    rs[f] = r;
    __syncthreads();
    if (f < DPf) {
        float o = fc2_b[f];
#pragma unroll 8
        for (int j = 0; j < DMf; j++) o += rs[j] * fc2_w[j*DPf + f];
        o += features[(size_t)row*DPf + f];
        out[(size_t)row*DPf + f] = o;
    }
}

// ---------------- launch ----------------
extern "C" void kernel_launch(void* const* d_in, const int* in_sizes, int n_in,
                              void* d_out, int out_size) {
    const float* xyz   = (const float*)d_in[0];
    const float* feat  = (const float*)d_in[1];
    const float* fc1_w = (const float*)d_in[2];
    const float* fc1_b = (const float*)d_in[3];
    const float* fc2_w = (const float*)d_in[4];
    const float* fc2_b = (const float*)d_in[5];
    const float* d1_w  = (const float*)d_in[6];
    const float* d1_b  = (const float*)d_in[7];
    const float* d2_w  = (const float*)d_in[8];
    const float* d2_b  = (const float*)d_in[9];
    const float* g1_w  = (const float*)d_in[10];
    const float* g1_b  = (const float*)d_in[11];
    const float* g2_w  = (const float*)d_in[12];
    const float* g2_b  = (const float*)d_in[13];
    const float* wq_w  = (const float*)d_in[14];
    const float* wk_w  = (const float*)d_in[15];
    const float* wv_w  = (const float*)d_in[16];
    const float* sim_w = (const float*)d_in[17];
    const float* sim_b = (const float*)d_in[18];
    float* out = (float*)d_out;

    static float *p_x = nullptr, *p_q, *p_kf, *p_vf;
    static bool attr_done = false;
    const int FUSED_SMEM = (2*BROWS*PITCH + BROWS*128) * 4;   // 100352 B
    if (!attr_done) {
        cudaGetSymbolAddress((void**)&p_x,  g_x);
        cudaGetSymbolAddress((void**)&p_q,  g_q);
        cudaGetSymbolAddress((void**)&p_kf, g_kf);
        cudaGetSymbolAddress((void**)&p_vf, g_vf);
        cudaFuncSetAttribute(fused_chain,
                             cudaFuncAttributeMaxDynamicSharedMemorySize, FUSED_SMEM);
        attr_done = true;
    }

    // 1) KNN
    knn_kernel<<<M1/4, 128>>>(xyz);

    // 2) x = features @ fc1 + b
    gemm_small<<<M1/128, 256>>>(feat, DPf, DPf, fc1_w, fc1_b, p_x,
                                nullptr, nullptr, nullptr, nullptr);

    // 3) q, k, v (batched)
    gemm_small<<<dim3(M1/128, 3), 256>>>(p_x, DMf, DMf, wq_w, nullptr, p_q,
                                         wk_w, p_kf, wv_w, p_vf);

    // 4) gather + sim + (q-k)->bufB + pos-enc hidden->bufA
    stage_d<<<M1/8, 256>>>(xyz, d1_w, d1_b);

    // 5-8) fused: pe + t + h2 + a  (a -> g_bufA, pe -> g_pe)
    fused_chain<<<M2/BROWS, 256, FUSED_SMEM>>>(d2_w, d2_b, sim_w, sim_b,
                                               g1_w, g1_b, g2_w, g2_b);

    // 9) softmax + weighted sum + fc2 + residual
    stage_f<<<M1, 128>>>(feat, fc2_w, fc2_b, out);
}